// round 16
// baseline (speedup 1.0000x reference)
#include <cuda_runtime.h>
#include <cuda_bf16.h>
#include <cstdint>

#define V_  262144
#define E_  524288
#define NG  8192
#define H_  128

// ---------------- tcgen05 feature gate ---------------------------------------------
#if defined(__CUDA_ARCH_FEAT_SM103_ALL) || defined(__CUDA_ARCH_FEAT_SM100_ALL) || defined(__CUDA_ARCH_FEAT_SM101_ALL)
#define HAS_TC 1
#endif
#if !defined(HAS_TC) && defined(__CUDA_ARCH_HAS_FEATURE__)
#if __CUDA_ARCH_HAS_FEATURE__(SM103_ALL)
#define HAS_TC 1
#endif
#endif
#ifndef HAS_TC
#define HAS_TC 0
#endif

// ---------------- scratch globals ------------------------------------------------
__device__ float    g_x[(size_t)V_ * H_];        // node features, fp32 (residual/head)
__device__ __align__(8) uint32_t g_xb[(size_t)V_ * 64];   // bf16x2 copy of x (scatter src)
__device__ __align__(8) uint32_t g_xab[(size_t)V_ * 64];  // bf16x2 x+agg accumulator
__device__ __align__(8) __nv_bfloat162 g_e2[(size_t)E_ * 64];  // edge emb, bf16x2
__device__ float    g_logit[V_];
__device__ float    g_den[NG];
// weights: transposed, bf16 hi/lo split, PRE-SWIZZLED (SW64) 32-K-chunk-contiguous
#define WT_TOTAL 204800
__device__ __align__(16) __nv_bfloat16 g_wbhi[WT_TOTAL];
__device__ __align__(16) __nv_bfloat16 g_wblo[WT_TOTAL];

// ---------------- PTX helpers -----------------------------------------------------
__device__ __forceinline__ uint32_t smem_u32(const void* p) {
    uint32_t a;
    asm("{ .reg .u64 t; cvta.to.shared.u64 t, %1; cvt.u32.u64 %0, t; }" : "=r"(a) : "l"(p));
    return a;
}
__device__ __forceinline__ void mbar_init(uint32_t mbar, uint32_t cnt) {
    asm volatile("mbarrier.init.shared.b64 [%0], %1;" :: "r"(mbar), "r"(cnt) : "memory");
}
__device__ __forceinline__ void mbar_arrive(uint32_t mbar) {
    asm volatile("mbarrier.arrive.shared.b64 _, [%0];" :: "r"(mbar) : "memory");
}
__device__ __forceinline__ void mbar_arrive_tx(uint32_t mbar, uint32_t tx) {
    asm volatile("mbarrier.arrive.expect_tx.shared.b64 _, [%0], %1;"
                 :: "r"(mbar), "r"(tx) : "memory");
}
__device__ __forceinline__ void mbar_wait(uint32_t mbar, uint32_t parity) {
    asm volatile(
        "{\n\t.reg .pred P;\n\tWL_%=:\n\t"
        "mbarrier.try_wait.parity.acquire.cta.shared::cta.b64 P, [%0], %1, 0x989680;\n\t"
        "@!P bra WL_%=;\n\t}" :: "r"(mbar), "r"(parity) : "memory");
}
__device__ __forceinline__ void fence_async_shared() {
    asm volatile("fence.proxy.async.shared::cta;" ::: "memory");
}
__device__ __forceinline__ void bulk_g2s(uint32_t dst, const void* src, uint32_t bytes,
                                         uint32_t mbar) {
    uint64_t gsrc;
    asm("cvta.to.global.u64 %0, %1;" : "=l"(gsrc) : "l"(src));
    asm volatile(
        "cp.async.bulk.shared::cta.global.mbarrier::complete_tx::bytes [%0], [%1], %2, [%3];"
        :: "r"(dst), "l"(gsrc), "r"(bytes), "r"(mbar) : "memory");
}

#if HAS_TC
__device__ __forceinline__ void mma_bf16(uint32_t d, uint64_t a, uint64_t b,
                                         uint32_t idesc, int acc) {
    asm volatile(
        "{\n\t.reg .pred p;\n\tsetp.ne.b32 p, %4, 0;\n\t"
        "tcgen05.mma.cta_group::1.kind::f16 [%0], %1, %2, %3, p;\n\t}"
        :: "r"(d), "l"(a), "l"(b), "r"(idesc), "r"(acc) : "memory");
}
__device__ __forceinline__ void mma_bf16_ts(uint32_t d, uint32_t a, uint64_t b,
                                            uint32_t idesc, int acc) {
    asm volatile(
        "{\n\t.reg .pred p;\n\tsetp.ne.b32 p, %4, 0;\n\t"
        "tcgen05.mma.cta_group::1.kind::f16 [%0], [%1], %2, %3, p;\n\t}"
        :: "r"(d), "r"(a), "l"(b), "r"(idesc), "r"(acc) : "memory");
}
__device__ __forceinline__ void tc_commit(uint32_t mbar) {
    asm volatile(
        "tcgen05.commit.cta_group::1.mbarrier::arrive::one.shared::cluster.b64 [%0];"
        :: "r"(mbar) : "memory");
}
__device__ __forceinline__ void tc_alloc(uint32_t smem_dst, uint32_t ncols) {
    asm volatile("tcgen05.alloc.cta_group::1.sync.aligned.shared::cta.b32 [%0], %1;"
                 :: "r"(smem_dst), "r"(ncols) : "memory");
}
__device__ __forceinline__ void tc_dealloc(uint32_t tmem, uint32_t ncols) {
    asm volatile("tcgen05.dealloc.cta_group::1.sync.aligned.b32 %0, %1;"
                 :: "r"(tmem), "r"(ncols));
}
__device__ __forceinline__ void tc_relinquish() {
    asm volatile("tcgen05.relinquish_alloc_permit.cta_group::1.sync.aligned;");
}
__device__ __forceinline__ void tc_fence_after() {
    asm volatile("tcgen05.fence::after_thread_sync;" ::: "memory");
}
__device__ __forceinline__ void tc_fence_before() {
    asm volatile("tcgen05.fence::before_thread_sync;" ::: "memory");
}
__device__ __forceinline__ void tc_wait_ld() {
    asm volatile("tcgen05.wait::ld.sync.aligned;" ::: "memory");
}
__device__ __forceinline__ void tc_wait_st() {
    asm volatile("tcgen05.wait::st.sync.aligned;" ::: "memory");
}
__device__ __forceinline__ void ldtm32(uint32_t* r, uint32_t addr) {
    asm volatile(
        "tcgen05.ld.sync.aligned.32x32b.x32.b32 "
        "{%0, %1, %2, %3, %4, %5, %6, %7, %8, %9, %10, %11, %12, %13, %14, %15, "
        " %16, %17, %18, %19, %20, %21, %22, %23, %24, %25, %26, %27, %28, %29, %30, %31}, [%32];"
        : "=r"(r[0]), "=r"(r[1]), "=r"(r[2]), "=r"(r[3]), "=r"(r[4]), "=r"(r[5]),
          "=r"(r[6]), "=r"(r[7]), "=r"(r[8]), "=r"(r[9]), "=r"(r[10]), "=r"(r[11]),
          "=r"(r[12]), "=r"(r[13]), "=r"(r[14]), "=r"(r[15]), "=r"(r[16]), "=r"(r[17]),
          "=r"(r[18]), "=r"(r[19]), "=r"(r[20]), "=r"(r[21]), "=r"(r[22]), "=r"(r[23]),
          "=r"(r[24]), "=r"(r[25]), "=r"(r[26]), "=r"(r[27]), "=r"(r[28]), "=r"(r[29]),
          "=r"(r[30]), "=r"(r[31])
        : "r"(addr));
}
__device__ __forceinline__ void ldtm16(uint32_t* r, uint32_t addr) {
    asm volatile(
        "tcgen05.ld.sync.aligned.32x32b.x16.b32 "
        "{%0, %1, %2, %3, %4, %5, %6, %7, %8, %9, %10, %11, %12, %13, %14, %15}, [%16];"
        : "=r"(r[0]), "=r"(r[1]), "=r"(r[2]), "=r"(r[3]), "=r"(r[4]), "=r"(r[5]),
          "=r"(r[6]), "=r"(r[7]), "=r"(r[8]), "=r"(r[9]), "=r"(r[10]), "=r"(r[11]),
          "=r"(r[12]), "=r"(r[13]), "=r"(r[14]), "=r"(r[15])
        : "r"(addr));
}
__device__ __forceinline__ void sttm8(uint32_t addr, const uint32_t* r) {
    asm volatile(
        "tcgen05.st.sync.aligned.32x32b.x8.b32 [%0], {%1, %2, %3, %4, %5, %6, %7, %8};"
        :: "r"(addr), "r"(r[0]), "r"(r[1]), "r"(r[2]), "r"(r[3]),
           "r"(r[4]), "r"(r[5]), "r"(r[6]), "r"(r[7]) : "memory");
}
#endif  // HAS_TC

// SW64 K-major descriptor: layout=4, version=1, SBO=32, LBO=1
static __device__ __forceinline__ uint64_t make_desc64(uint32_t addr) {
    const uint64_t base =
        (uint64_t(4) << 61) | (uint64_t(1) << 46) | (uint64_t(32) << 32) | (uint64_t(1) << 16);
    return base | ((uint64_t)(addr >> 4) & 0x3FFF);
}

// idesc kind::f16: cF32(1<<4) | aBF16(1<<7) | bBF16(1<<10) | N=128 (16<<17) | M=128 (8<<24)
#define IDESC_BF16 0x08200490u

// ------- streaming GEMM smem layout (EMB / HEAD) -------
#define SM_TMEMP 0
#define SM_FULL0 16
#define SM_FULL1 24
#define SM_EMPT0 32
#define SM_EMPT1 40
#define SM_PART  256
#define SM_TILES 2048
#define STG_SZ   32768
#define OFF_AHI  0
#define OFF_ALO  8192
#define OFF_BHI  16384
#define OFF_BLO  24576
#define SMEM_GEMM (SM_TILES + 2 * STG_SZ)

// ------- fused layer smem layout (R12 structure: resident W per phase, TS phase 2) -
#define L_F1    16           // + c*8
#define L_F2A   48
#define L_D1DN  56
#define L_E2DN  64
#define L_WBAR  72
#define L_B1S   128          // 512B
#define L_ASTG  1024         // + c*8192 : A hi stage per chunk (4 x 8KB)
#define L_WHI   33792        // 32KB resident W hi
#define L_WLO   66560        // 32KB resident W lo
#define SMEM_LAYER 99328
// TMEM: D1/D2 cols 0-127, A2hi 128-191, A2lo 192-255
#define TM_A2H  128
#define TM_A2L  192

__device__ __forceinline__ uint32_t pack_bf2(float a, float b) {
    __nv_bfloat162 h = __float22bfloat162_rn(make_float2(a, b));
    return *(uint32_t*)&h;
}

// ---------------- weight split (+ softmax scratch zero) ---------------------------
__global__ void split_w_k(const float* __restrict__ We, const float* __restrict__ W1,
                          const float* __restrict__ W2, const float* __restrict__ Wm)
{
    int i = blockIdx.x * 256 + threadIdx.x;
    if (i >= WT_TOTAL) return;
    if (i < NG) g_den[i] = 0.f;
    int base, n, k, K;
    if (i < 49152)       { base = 0;      int j = i;          K = 384; n = j / K; k = j % K; }
    else if (i < 114688) { int j = i - 49152;  int l = j >> 14; base = 49152 + l*16384;  j &= 16383; K = 128; n = j >> 7; k = j & 127; }
    else if (i < 180224) { int j = i - 114688; int l = j >> 14; base = 114688 + l*16384; j &= 16383; K = 128; n = j >> 7; k = j & 127; }
    else                 { base = 180224; int j = i - 180224;  K = 192; n = j / K; k = j % K; }
    float v;
    if (base == 0)           v = We[k * 128 + n];
    else if (base < 114688)  v = W1[(base - 49152) / 16384 * 16384 + k * 128 + n];
    else if (base < 180224)  v = W2[(base - 114688) / 16384 * 16384 + k * 128 + n];
    else                     v = Wm[k * 128 + n];

    __nv_bfloat16 hi = __float2bfloat16_rn(v);
    __nv_bfloat16 lo = __float2bfloat16_rn(v - __bfloat162float(hi));
    int chunk = k >> 5, kk = k & 31;
    uint32_t off = (uint32_t)n * 64u + (uint32_t)kk * 2u;
    off ^= ((off >> 3) & 0x30);               // SW64 swizzle
    int di = base + chunk * 4096 + (int)(off >> 1);
    g_wbhi[di] = hi;
    g_wblo[di] = lo;
}

// ---------------- scatter: xab[dst] += bf16(relu(xb[src] + e)) --------------------
__global__ __launch_bounds__(256) void scatter_k(
    const int* __restrict__ src, const int* __restrict__ dst)
{
    const int warp = (blockIdx.x * blockDim.x + threadIdx.x) >> 5;
    const int lane = threadIdx.x & 31;
    if (warp >= E_) return;
    const int s = src[warp];
    const int d = dst[warp];
    uint2 xv = *(const uint2*)(g_xb + (size_t)s * 64 + lane * 2);
    float2 x0 = __bfloat1622float2(*(__nv_bfloat162*)&xv.x);
    float2 x1 = __bfloat1622float2(*(__nv_bfloat162*)&xv.y);
    const __nv_bfloat162* ep = g_e2 + (size_t)warp * 64 + lane * 2;
    float2 e0 = __bfloat1622float2(ep[0]);
    float2 e1 = __bfloat1622float2(ep[1]);
    __nv_bfloat162 m0 = __float22bfloat162_rn(
        make_float2(fmaxf(x0.x + e0.x, 0.f), fmaxf(x0.y + e0.y, 0.f)));
    __nv_bfloat162 m1 = __float22bfloat162_rn(
        make_float2(fmaxf(x1.x + e1.x, 0.f), fmaxf(x1.y + e1.y, 0.f)));
    __nv_bfloat162* ap = (__nv_bfloat162*)(g_xab + (size_t)d * 64 + lane * 2);
    atomicAdd(ap,     m0);
    atomicAdd(ap + 1, m1);
}

// ---------------- EMB(+edge blocks) / HEAD GEMM (streaming B pipeline) ------------
template <int K, int MODE>
__global__ __launch_bounds__(288, 2) void tc_gemm_k(
    const float* __restrict__ A0, const float* __restrict__ A1,
    const float* __restrict__ A2, const int* __restrict__ n2g,
    const float* __restrict__ bias, const float* __restrict__ w2,
    const float* __restrict__ b2s, const float* __restrict__ eattr, int woff)
{
    extern __shared__ __align__(1024) char smem[];
    const int tid  = threadIdx.x;

    // ---------------- edge-embedding blocks (MODE 0 only) ----------------
    if (MODE == 0 && blockIdx.x >= V_ / 128) {
        const int eb = blockIdx.x - V_ / 128;
        const int e0 = eb * 256;
        float* Ws = (float*)smem;
        float* Ae = (float*)(smem + 8192);
        float* bs = (float*)(smem + 24576);
        for (int i = tid; i < 2048; i += 288) Ws[i] = w2[i];
        for (int i = tid; i < 4096; i += 288) Ae[i] = eattr[(size_t)e0 * 16 + i];
        if (tid < 128) bs[tid] = b2s[tid];
        __syncthreads();
        if (tid < 256) {
            const int col = tid & 127, half = tid >> 7;
            float w[16];
            #pragma unroll
            for (int k = 0; k < 16; k++) w[k] = Ws[k * 128 + col];
            const float bb = bs[col];
            for (int ee = 0; ee < 128; ee++) {
                const int e = half * 128 + ee;
                const float4* a4 = (const float4*)&Ae[e * 16];
                float4 x0 = a4[0], x1 = a4[1], x2 = a4[2], x3 = a4[3];
                float s = bb;
                s = fmaf(x0.x, w[0],  s); s = fmaf(x0.y, w[1],  s);
                s = fmaf(x0.z, w[2],  s); s = fmaf(x0.w, w[3],  s);
                s = fmaf(x1.x, w[4],  s); s = fmaf(x1.y, w[5],  s);
                s = fmaf(x1.z, w[6],  s); s = fmaf(x1.w, w[7],  s);
                s = fmaf(x2.x, w[8],  s); s = fmaf(x2.y, w[9],  s);
                s = fmaf(x2.z, w[10], s); s = fmaf(x2.w, w[11], s);
                s = fmaf(x3.x, w[12], s); s = fmaf(x3.y, w[13], s);
                s = fmaf(x3.z, w[14], s); s = fmaf(x3.w, w[15], s);
                s = fmaxf(s, 0.f);
                float snb = __shfl_down_sync(0xffffffffu, s, 1);
                if ((col & 1) == 0) {
                    uint32_t pk = pack_bf2(s, snb);
                    *(uint32_t*)&g_e2[(size_t)(e0 + e) * 64 + (col >> 1)] = pk;
                }
            }
        }
        return;
    }

#if HAS_TC
    const uint32_t sb = smem_u32(smem);
    const int wid  = tid >> 5;
    const int lane = tid & 31;
    const int rowBase = blockIdx.x * 128;
    const int NCH = K / 32;

    if (wid == 0) { tc_alloc(sb + SM_TMEMP, 128); tc_relinquish(); }
    if (tid == 0) {
        mbar_init(sb + SM_FULL0, 257); mbar_init(sb + SM_FULL1, 257);
        mbar_init(sb + SM_EMPT0, 1);   mbar_init(sb + SM_EMPT1, 1);
    }
    __syncthreads();
    uint32_t tmem;
    asm volatile("ld.shared.b32 %0, [%1];" : "=r"(tmem) : "r"(sb + SM_TMEMP));

    if (tid < 256) {
        const int row  = tid >> 1;
        const int r    = rowBase + row;
        const int half = tid & 1;
        uint32_t bo = (uint32_t)row * 64u + (uint32_t)half * 32u;
        const uint32_t sw0 = bo ^ ((bo >> 3) & 0x30);
        bo += 16u;
        const uint32_t sw1 = bo ^ ((bo >> 3) & 0x30);
        int gg = 0;
        if (MODE == 0) gg = __ldg(n2g + r);

        for (int c = 0; c < NCH; c++) {
            const int s = c & 1;
            const int kb = c * 32 + half * 16;
            float4 av[4];
            if (MODE == 0) {
                const float* p = (kb < 128) ? A0 + (size_t)r * 128 + kb
                               : (kb < 256) ? A1 + (size_t)gg * 128 + (kb - 128)
                                            : A2 + (size_t)gg * 128 + (kb - 256);
                #pragma unroll
                for (int q = 0; q < 4; q++) av[q] = *(const float4*)(p + q * 4);
            } else {
                const float* p = (kb < 128) ? g_x + (size_t)r * 128 + kb
                                            : A0 + (size_t)r * 64 + (kb - 128);
                #pragma unroll
                for (int q = 0; q < 4; q++) av[q] = *(const float4*)(p + q * 4);
            }

            if (c >= 2) mbar_wait(sb + SM_EMPT0 + s * 8, ((c >> 1) + 1) & 1);

            const float* f = (const float*)av;
            uint32_t hi[8], lo[8];
            #pragma unroll
            for (int q = 0; q < 8; q++) {
                float a = f[2 * q], b = f[2 * q + 1];
                __nv_bfloat162 h = __float22bfloat162_rn(make_float2(a, b));
                hi[q] = *(uint32_t*)&h;
                lo[q] = pack_bf2(a - __bfloat162float(h.x), b - __bfloat162float(h.y));
            }
            char* stg = smem + SM_TILES + s * STG_SZ;
            *(uint4*)(stg + OFF_AHI + sw0) = *(uint4*)&hi[0];
            *(uint4*)(stg + OFF_AHI + sw1) = *(uint4*)&hi[4];
            *(uint4*)(stg + OFF_ALO + sw0) = *(uint4*)&lo[0];
            *(uint4*)(stg + OFF_ALO + sw1) = *(uint4*)&lo[4];

            fence_async_shared();
            mbar_arrive(sb + SM_FULL0 + s * 8);
        }
    } else if (tid == 256) {
        uint64_t dAhi[2], dAlo[2], dBhi[2], dBlo[2];
        #pragma unroll
        for (int s = 0; s < 2; s++) {
            uint32_t st = sb + SM_TILES + s * STG_SZ;
            dAhi[s] = make_desc64(st + OFF_AHI);
            dAlo[s] = make_desc64(st + OFF_ALO);
            dBhi[s] = make_desc64(st + OFF_BHI);
            dBlo[s] = make_desc64(st + OFF_BLO);
        }
        for (int c = 0; c < NCH; c++) {
            const int s = c & 1;
            if (c >= 2) mbar_wait(sb + SM_EMPT0 + s * 8, ((c >> 1) + 1) & 1);
            const uint32_t full = sb + SM_FULL0 + s * 8;
            mbar_arrive_tx(full, 16384);
            const uint32_t st = sb + SM_TILES + s * STG_SZ;
            bulk_g2s(st + OFF_BHI, g_wbhi + woff + c * 4096, 8192, full);
            bulk_g2s(st + OFF_BLO, g_wblo + woff + c * 4096, 8192, full);
            mbar_wait(full, (c >> 1) & 1);
            #pragma unroll
            for (int ks = 0; ks < 2; ks++) {
                const uint64_t o = ks * 2;
                int first = (c == 0 && ks == 0);
                mma_bf16(tmem, dAhi[s] + o, dBhi[s] + o, IDESC_BF16, first ? 0 : 1);
                mma_bf16(tmem, dAhi[s] + o, dBlo[s] + o, IDESC_BF16, 1);
                mma_bf16(tmem, dAlo[s] + o, dBhi[s] + o, IDESC_BF16, 1);
            }
            tc_commit(sb + SM_EMPT0 + s * 8);
        }
    }

    {
        const int L = NCH - 1;
        mbar_wait(sb + SM_EMPT0 + (L & 1) * 8, (L >> 1) & 1);
        tc_fence_after();
    }
    if (tid < 256) {
        const int sp = wid & 3;
        const int h  = wid >> 2;
        const int r  = rowBase + sp * 32 + lane;
        const int cb = h * 64;
        uint32_t regs[64];
        ldtm32(regs,      tmem + cb);
        ldtm32(regs + 32, tmem + cb + 32);
        tc_wait_ld();

        if (MODE == 3) {
            float p = 0.f;
            #pragma unroll
            for (int j = 0; j < 64; j++) {
                float t = fmaxf(__uint_as_float(regs[j]) + __ldg(bias + cb + j), 0.f);
                p = fmaf(t, __ldg(w2 + cb + j), p);
            }
            ((float*)(smem + SM_PART))[h * 128 + sp * 32 + lane] = p;
        } else {
            size_t base = (size_t)r * 128 + cb;
            #pragma unroll
            for (int j = 0; j < 64; j += 4) {
                float4 o;
                o.x = fmaxf(__uint_as_float(regs[j + 0]) + __ldg(bias + cb + j + 0), 0.f);
                o.y = fmaxf(__uint_as_float(regs[j + 1]) + __ldg(bias + cb + j + 1), 0.f);
                o.z = fmaxf(__uint_as_float(regs[j + 2]) + __ldg(bias + cb + j + 2), 0.f);
                o.w = fmaxf(__uint_as_float(regs[j + 3]) + __ldg(bias + cb + j + 3), 0.f);
                *(float4*)(g_x + base + j) = o;
                uint2 pk;
                pk.x = pack_bf2(o.x, o.y);
                pk.y = pack_bf2(o.z, o.w);
                size_t pbase = (size_t)r * 64 + ((cb + j) >> 1);
                *(uint2*)(g_xab + pbase) = pk;
                *(uint2*)(g_xb  + pbase) = pk;
            }
        }
    }
    __syncthreads();
    if (MODE == 3 && tid < 128) {
        const float* part = (const float*)(smem + SM_PART);
        g_logit[rowBase + tid] = part[tid] + part[128 + tid] + b2s[0];
    }
    if (wid == 0) tc_dealloc(tmem, 128);

#else  // fallback (family-PTX pass only)
    const int rowBase = blockIdx.x * 128;
    if (tid >= 128) return;
    __shared__ float col[128];
    for (int m = 0; m < 128; m++) {
        const int r = rowBase + m;
        float acc = 0.f;
        for (int k = 0; k < K; k++) {
            float a;
            if (MODE == 0) {
                if (k < 128) a = A0[(size_t)r * 128 + k];
                else {
                    int gg = n2g[r];
                    a = (k < 256) ? A1[(size_t)gg * 128 + (k - 128)]
                                  : A2[(size_t)gg * 128 + (k - 256)];
                }
            } else {
                a = (k < 128) ? g_x[(size_t)r * 128 + k] : A0[(size_t)r * 64 + (k - 128)];
            }
            int chunk = k >> 5, kk = k & 31;
            uint32_t off = (uint32_t)tid * 64u + (uint32_t)kk * 2u;
            off ^= ((off >> 3) & 0x30);
            int di = woff + chunk * 4096 + (int)(off >> 1);
            float w = __bfloat162float(g_wbhi[di]) + __bfloat162float(g_wblo[di]);
            acc = fmaf(a, w, acc);
        }
        if (MODE == 3) {
            col[tid] = fmaxf(acc + bias[tid], 0.f) * w2[tid];
            __syncthreads();
            if (tid == 0) {
                float p = 0.f;
                for (int j = 0; j < 128; j++) p += col[j];
                g_logit[r] = p + b2s[0];
            }
            __syncthreads();
        } else {
            float o = fmaxf(acc + bias[tid], 0.f);
            g_x[(size_t)r * 128 + tid] = o;
            if ((tid & 1) == 0) {
                uint32_t pk = pack_bf2(o, fmaxf(0.f, 0.f));  // placeholder low half
                (void)pk;
            }
            // simple per-element bf16 mirror (correct, slow; never runs on device)
            __nv_bfloat16 ob = __float2bfloat16_rn(o);
            ((__nv_bfloat16*)g_xab)[(size_t)r * 128 + tid] = ob;
            ((__nv_bfloat16*)g_xb)[(size_t)r * 128 + tid]  = ob;
        }
    }
#endif
}

// ---------------- fused GINE layer (R12 structure; xab bf16 input) ----------------
// x += relu(relu(xab@W1+b1)@W2+b2); phase1 2-term (A=xab bf16), phase2 3-term TS.
__global__ __launch_bounds__(288, 2) void tc_layer_k(
    const float* __restrict__ b1, const float* __restrict__ b2,
    int woff1, int woff2, int seed)
{
#if HAS_TC
    extern __shared__ __align__(1024) char smem[];
    const uint32_t sb = smem_u32(smem);
    const int tid  = threadIdx.x;
    const int wid  = tid >> 5;
    const int lane = tid & 31;
    const int rowBase = blockIdx.x * 128;
    float* b1s = (float*)(smem + L_B1S);

    if (wid == 0) { tc_alloc(sb, 256); tc_relinquish(); }
    if (tid == 0) {
        #pragma unroll
        for (int c = 0; c < 4; c++) mbar_init(sb + L_F1 + c * 8, 256);
        mbar_init(sb + L_F2A, 256);
        mbar_init(sb + L_D1DN, 1);
        mbar_init(sb + L_E2DN, 1);
        mbar_init(sb + L_WBAR, 1);
    }
    if (tid >= 128 && tid < 256) b1s[tid - 128] = b1[tid - 128];
    __syncthreads();
    uint32_t tmem;
    asm volatile("ld.shared.b32 %0, [%1];" : "=r"(tmem) : "r"(sb));

    // ============ phase 1: D1 = xab(bf16) @ W1 — pure copy producers ============
    if (tid < 256) {
        const int row  = tid >> 1;
        const int r    = rowBase + row;
        const int half = tid & 1;
        uint32_t bo = (uint32_t)row * 64u + (uint32_t)half * 32u;
        const uint32_t sw0 = bo ^ ((bo >> 3) & 0x30);
        bo += 16u;
        const uint32_t sw1 = bo ^ ((bo >> 3) & 0x30);

        #pragma unroll
        for (int c = 0; c < 4; c++) {
            const uint32_t* p = g_xab + (size_t)r * 64 + c * 16 + half * 8;
            uint4 v0 = *(const uint4*)p;
            uint4 v1 = *(const uint4*)(p + 4);
            char* stg = smem + L_ASTG + c * 8192;
            *(uint4*)(stg + sw0) = v0;
            *(uint4*)(stg + sw1) = v1;
            fence_async_shared();
            mbar_arrive(sb + L_F1 + c * 8);
        }
    } else if (tid == 256) {
        mbar_arrive_tx(sb + L_WBAR, 65536);
        bulk_g2s(sb + L_WHI, g_wbhi + woff1, 32768, sb + L_WBAR);
        bulk_g2s(sb + L_WLO, g_wblo + woff1, 32768, sb + L_WBAR);
        uint64_t dA[4];
        #pragma unroll
        for (int c = 0; c < 4; c++) dA[c] = make_desc64(sb + L_ASTG + c * 8192);
        mbar_wait(sb + L_WBAR, 0);
        for (int c = 0; c < 4; c++) {
            mbar_wait(sb + L_F1 + c * 8, 0);
            uint64_t bh = make_desc64(sb + L_WHI + c * 8192);
            uint64_t bl = make_desc64(sb + L_WLO + c * 8192);
            #pragma unroll
            for (int ks = 0; ks < 2; ks++) {
                const uint64_t o = ks * 2;
                int first = (c == 0 && ks == 0);
                mma_bf16(tmem, dA[c] + o, bh + o, IDESC_BF16, first ? 0 : 1);
                mma_bf16(tmem, dA[c] + o, bl + o, IDESC_BF16, 1);
            }
        }
        tc_commit(sb + L_D1DN);
        // W2 load overlaps producers' A2 conversion (W1 reads drained at D1DN)
        mbar_wait(sb + L_D1DN, 0);
        mbar_arrive_tx(sb + L_WBAR, 65536);
        bulk_g2s(sb + L_WHI, g_wbhi + woff2, 32768, sb + L_WBAR);
        bulk_g2s(sb + L_WLO, g_wblo + woff2, 32768, sb + L_WBAR);
        mbar_wait(sb + L_WBAR, 1);
        mbar_wait(sb + L_F2A, 0);
        tc_fence_after();
        for (int c = 0; c < 4; c++) {
            uint64_t bh = make_desc64(sb + L_WHI + c * 8192);
            uint64_t bl = make_desc64(sb + L_WLO + c * 8192);
            #pragma unroll
            for (int ks = 0; ks < 2; ks++) {
                const uint64_t o = ks * 2;
                const uint32_t aH = tmem + TM_A2H + c * 16 + ks * 8;
                const uint32_t aL = tmem + TM_A2L + c * 16 + ks * 8;
                int first = (c == 0 && ks == 0);
                mma_bf16_ts(tmem, aH, bh + o, IDESC_BF16, first ? 0 : 1);
                mma_bf16_ts(tmem, aH, bl + o, IDESC_BF16, 1);
                mma_bf16_ts(tmem, aL, bh + o, IDESC_BF16, 1);
            }
        }
        tc_commit(sb + L_E2DN);
    }

    // ============ phase 2 producers: A2 = hi/lo(relu(D1 + b1)) -> TMEM ============
    if (tid < 256) {
        mbar_wait(sb + L_D1DN, 0);
        tc_fence_after();
        const int sp = wid & 3;
        const int hh = wid >> 2;
        const uint32_t woffT = (uint32_t)sp << 21;
        #pragma unroll
        for (int c = 0; c < 4; c++) {
            uint32_t regs[16];
            ldtm16(regs, tmem + c * 32 + hh * 16);
            tc_wait_ld();
            const int cb = c * 32 + hh * 16;
            uint32_t ahi[8], alo[8];
            #pragma unroll
            for (int q = 0; q < 8; q++) {
                float a = fmaxf(__uint_as_float(regs[2 * q])     + b1s[cb + 2 * q],     0.f);
                float b = fmaxf(__uint_as_float(regs[2 * q + 1]) + b1s[cb + 2 * q + 1], 0.f);
                __nv_bfloat162 h = __float22bfloat162_rn(make_float2(a, b));
                ahi[q] = *(uint32_t*)&h;
                alo[q] = pack_bf2(a - __bfloat162float(h.x), b - __bfloat162float(h.y));
            }
            sttm8(tmem + woffT + TM_A2H + c * 16 + hh * 8, ahi);
            sttm8(tmem + woffT + TM_A2L + c * 16 + hh * 8, alo);
        }
        tc_wait_st();
        tc_fence_before();
        mbar_arrive(sb + L_F2A);
    }

    // ============ epilogue: g_x += relu(D2 + b2); seed bf16 mirrors ============
    mbar_wait(sb + L_E2DN, 0);
    tc_fence_after();
    if (tid < 256) {
        const int sp = wid & 3;
        const int h  = wid >> 2;
        const int r  = rowBase + sp * 32 + lane;
        const int cb = h * 64;
        uint32_t regs[64];
        ldtm32(regs,      tmem + cb);            // D2 lives in cols 0-127
        ldtm32(regs + 32, tmem + cb + 32);
        tc_wait_ld();
        size_t base = (size_t)r * 128 + cb;
        #pragma unroll
        for (int j = 0; j < 64; j += 4) {
            float4 o;
            o.x = fmaxf(__uint_as_float(regs[j + 0]) + __ldg(b2 + cb + j + 0), 0.f);
            o.y = fmaxf(__uint_as_float(regs[j + 1]) + __ldg(b2 + cb + j + 1), 0.f);
            o.z = fmaxf(__uint_as_float(regs[j + 2]) + __ldg(b2 + cb + j + 2), 0.f);
            o.w = fmaxf(__uint_as_float(regs[j + 3]) + __ldg(b2 + cb + j + 3), 0.f);
            float4 x0 = *(const float4*)(g_x + base + j);
            o.x += x0.x; o.y += x0.y; o.z += x0.z; o.w += x0.w;
            *(float4*)(g_x + base + j) = o;
            if (seed) {
                uint2 pk;
                pk.x = pack_bf2(o.x, o.y);
                pk.y = pack_bf2(o.z, o.w);
                size_t pbase = (size_t)r * 64 + ((cb + j) >> 1);
                *(uint2*)(g_xab + pbase) = pk;
                *(uint2*)(g_xb  + pbase) = pk;
            }
        }
    }
    __syncthreads();
    if (wid == 0) tc_dealloc(tmem, 256);

#else  // fallback (family-PTX pass only)
    const int tid = threadIdx.x;
    const int rowBase = blockIdx.x * 128;
    if (tid >= 128) return;
    __shared__ float hrow[128];
    for (int m = 0; m < 128; m++) {
        const int r = rowBase + m;
        float acc = 0.f;
        for (int k = 0; k < 128; k++) {
            float a = __bfloat162float(((__nv_bfloat16*)g_xab)[(size_t)r * 128 + k]);
            int chunk = k >> 5, kk = k & 31;
            uint32_t off = (uint32_t)tid * 64u + (uint32_t)kk * 2u;
            off ^= ((off >> 3) & 0x30);
            int di = woff1 + chunk * 4096 + (int)(off >> 1);
            acc = fmaf(a, __bfloat162float(g_wbhi[di]) + __bfloat162float(g_wblo[di]), acc);
        }
        hrow[tid] = fmaxf(acc + b1[tid], 0.f);
        __syncthreads();
        float acc2 = 0.f;
        for (int k = 0; k < 128; k++) {
            int chunk = k >> 5, kk = k & 31;
            uint32_t off = (uint32_t)tid * 64u + (uint32_t)kk * 2u;
            off ^= ((off >> 3) & 0x30);
            int di = woff2 + chunk * 4096 + (int)(off >> 1);
            acc2 = fmaf(hrow[k], __bfloat162float(g_wbhi[di]) + __bfloat162float(g_wblo[di]), acc2);
        }
        float xn = g_x[(size_t)r * 128 + tid] + fmaxf(acc2 + b2[tid], 0.f);
        g_x[(size_t)r * 128 + tid] = xn;
        if (seed) {
            __nv_bfloat16 xb = __float2bfloat16_rn(xn);
            ((__nv_bfloat16*)g_xab)[(size_t)r * 128 + tid] = xb;
            ((__nv_bfloat16*)g_xb)[(size_t)r * 128 + tid]  = xb;
        }
        __syncthreads();
    }
#endif
}

// ---------------- segment softmax (no max pass; logits are O(1)) -------------------
__global__ void seg_exp_k(const int* __restrict__ n2g, float* __restrict__ out) {
    int i = blockIdx.x * blockDim.x + threadIdx.x;
    if (i >= V_) return;
    float ex = expf(g_logit[i]);
    out[i] = ex;
    atomicAdd(&g_den[n2g[i]], ex);
}
__global__ void seg_div_k(const int* __restrict__ n2g, float* __restrict__ out) {
    int i = blockIdx.x * blockDim.x + threadIdx.x;
    if (i >= V_) return;
    out[i] = out[i] / g_den[n2g[i]];
}

// ---------------- launch -----------------------------------------------------------
extern "C" void kernel_launch(void* const* d_in, const int* in_sizes, int n_in,
                              void* d_out, int out_size)
{
    const float* x_inp   = (const float*)d_in[0];
    const int*   eidx    = (const int*)  d_in[1];
    const float* eattr   = (const float*)d_in[2];
    const float* x_upd   = (const float*)d_in[3];
    const float* Zc      = (const float*)d_in[4];
    const float* Zb      = (const float*)d_in[5];
    const int*   n2g     = (const int*)  d_in[6];
    const float* W_emb   = (const float*)d_in[7];
    const float* b_emb   = (const float*)d_in[8];
    const float* W_edge  = (const float*)d_in[9];
    const float* b_edge  = (const float*)d_in[10];
    const float* W1      = (const float*)d_in[11];
    const float* b1      = (const float*)d_in[12];
    const float* W2      = (const float*)d_in[13];
    const float* b2      = (const float*)d_in[14];
    const float* W_mlp1  = (const float*)d_in[15];
    const float* b_mlp1  = (const float*)d_in[16];
    const float* W_mlp2  = (const float*)d_in[17];
    const float* b_mlp2  = (const float*)d_in[18];
    float* out = (float*)d_out;

    cudaFuncSetAttribute(tc_gemm_k<384, 0>, cudaFuncAttributeMaxDynamicSharedMemorySize, SMEM_GEMM);
    cudaFuncSetAttribute(tc_gemm_k<192, 3>, cudaFuncAttributeMaxDynamicSharedMemorySize, SMEM_GEMM);
    cudaFuncSetAttribute(tc_layer_k,        cudaFuncAttributeMaxDynamicSharedMemorySize, SMEM_LAYER);

    const int GB = V_ / 128;   // 2048 tiles

    split_w_k<<<(WT_TOTAL + 255) / 256, 256>>>(W_emb, W1, W2, W_mlp1);
    tc_gemm_k<384, 0><<<GB + 2048, 288, SMEM_GEMM>>>(x_upd, Zc, Zb, n2g, b_emb,
                                                     W_edge, b_edge, eattr, 0);
    for (int l = 0; l < 4; l++) {
        scatter_k<<<E_ / 8, 256>>>(eidx, eidx + E_);
        tc_layer_k<<<GB, 288, SMEM_LAYER>>>(b1 + (size_t)l * 128, b2 + (size_t)l * 128,
                                            49152 + l * 16384, 114688 + l * 16384,
                                            l < 3 ? 1 : 0);
    }
    tc_gemm_k<192, 3><<<GB, 288, SMEM_GEMM>>>(x_inp, nullptr, nullptr, nullptr,
                                              b_mlp1, W_mlp2, b_mlp2, nullptr, 180224);

    seg_exp_k<<<V_ / 256, 256>>>(n2g, out);
    seg_div_k<<<V_ / 256, 256>>>(n2g, out);
}

// round 17
// speedup vs baseline: 1.0948x; 1.0948x over previous
#include <cuda_runtime.h>
#include <cuda_bf16.h>
#include <cstdint>

#define V_  262144
#define E_  524288
#define NG  8192
#define H_  128

// ---------------- tcgen05 feature gate ---------------------------------------------
#if defined(__CUDA_ARCH_FEAT_SM103_ALL) || defined(__CUDA_ARCH_FEAT_SM100_ALL) || defined(__CUDA_ARCH_FEAT_SM101_ALL)
#define HAS_TC 1
#endif
#if !defined(HAS_TC) && defined(__CUDA_ARCH_HAS_FEATURE__)
#if __CUDA_ARCH_HAS_FEATURE__(SM103_ALL)
#define HAS_TC 1
#endif
#endif
#ifndef HAS_TC
#define HAS_TC 0
#endif

// ---------------- scratch globals ------------------------------------------------
__device__ float    g_x[(size_t)V_ * H_];     // current node features
__device__ float    g_xa[(size_t)V_ * H_];    // x + aggregated messages (seeded w/ x)
__device__ __align__(8) __nv_bfloat162 g_e2[(size_t)E_ * 64];  // edge emb, bf16x2
__device__ float    g_den[NG];
// weights: transposed, bf16 hi/lo split, PRE-SWIZZLED (SW64) 32-K-chunk-contiguous
#define WT_TOTAL 204800
__device__ __align__(16) __nv_bfloat16 g_wbhi[WT_TOTAL];
__device__ __align__(16) __nv_bfloat16 g_wblo[WT_TOTAL];

// ---------------- PTX helpers -----------------------------------------------------
__device__ __forceinline__ uint32_t smem_u32(const void* p) {
    uint32_t a;
    asm("{ .reg .u64 t; cvta.to.shared.u64 t, %1; cvt.u32.u64 %0, t; }" : "=r"(a) : "l"(p));
    return a;
}
__device__ __forceinline__ void mbar_init(uint32_t mbar, uint32_t cnt) {
    asm volatile("mbarrier.init.shared.b64 [%0], %1;" :: "r"(mbar), "r"(cnt) : "memory");
}
__device__ __forceinline__ void mbar_arrive(uint32_t mbar) {
    asm volatile("mbarrier.arrive.shared.b64 _, [%0];" :: "r"(mbar) : "memory");
}
__device__ __forceinline__ void mbar_arrive_tx(uint32_t mbar, uint32_t tx) {
    asm volatile("mbarrier.arrive.expect_tx.shared.b64 _, [%0], %1;"
                 :: "r"(mbar), "r"(tx) : "memory");
}
__device__ __forceinline__ void mbar_wait(uint32_t mbar, uint32_t parity) {
    asm volatile(
        "{\n\t.reg .pred P;\n\tWL_%=:\n\t"
        "mbarrier.try_wait.parity.acquire.cta.shared::cta.b64 P, [%0], %1, 0x989680;\n\t"
        "@!P bra WL_%=;\n\t}" :: "r"(mbar), "r"(parity) : "memory");
}
__device__ __forceinline__ void fence_async_shared() {
    asm volatile("fence.proxy.async.shared::cta;" ::: "memory");
}
__device__ __forceinline__ void bulk_g2s(uint32_t dst, const void* src, uint32_t bytes,
                                         uint32_t mbar) {
    uint64_t gsrc;
    asm("cvta.to.global.u64 %0, %1;" : "=l"(gsrc) : "l"(src));
    asm volatile(
        "cp.async.bulk.shared::cta.global.mbarrier::complete_tx::bytes [%0], [%1], %2, [%3];"
        :: "r"(dst), "l"(gsrc), "r"(bytes), "r"(mbar) : "memory");
}

#if HAS_TC
__device__ __forceinline__ void mma_bf16(uint32_t d, uint64_t a, uint64_t b,
                                         uint32_t idesc, int acc) {
    asm volatile(
        "{\n\t.reg .pred p;\n\tsetp.ne.b32 p, %4, 0;\n\t"
        "tcgen05.mma.cta_group::1.kind::f16 [%0], %1, %2, %3, p;\n\t}"
        :: "r"(d), "l"(a), "l"(b), "r"(idesc), "r"(acc) : "memory");
}
__device__ __forceinline__ void mma_bf16_ts(uint32_t d, uint32_t a, uint64_t b,
                                            uint32_t idesc, int acc) {
    asm volatile(
        "{\n\t.reg .pred p;\n\tsetp.ne.b32 p, %4, 0;\n\t"
        "tcgen05.mma.cta_group::1.kind::f16 [%0], [%1], %2, %3, p;\n\t}"
        :: "r"(d), "r"(a), "l"(b), "r"(idesc), "r"(acc) : "memory");
}
__device__ __forceinline__ void tc_commit(uint32_t mbar) {
    asm volatile(
        "tcgen05.commit.cta_group::1.mbarrier::arrive::one.shared::cluster.b64 [%0];"
        :: "r"(mbar) : "memory");
}
__device__ __forceinline__ void tc_alloc(uint32_t smem_dst, uint32_t ncols) {
    asm volatile("tcgen05.alloc.cta_group::1.sync.aligned.shared::cta.b32 [%0], %1;"
                 :: "r"(smem_dst), "r"(ncols) : "memory");
}
__device__ __forceinline__ void tc_dealloc(uint32_t tmem, uint32_t ncols) {
    asm volatile("tcgen05.dealloc.cta_group::1.sync.aligned.b32 %0, %1;"
                 :: "r"(tmem), "r"(ncols));
}
__device__ __forceinline__ void tc_relinquish() {
    asm volatile("tcgen05.relinquish_alloc_permit.cta_group::1.sync.aligned;");
}
__device__ __forceinline__ void tc_fence_after() {
    asm volatile("tcgen05.fence::after_thread_sync;" ::: "memory");
}
__device__ __forceinline__ void tc_fence_before() {
    asm volatile("tcgen05.fence::before_thread_sync;" ::: "memory");
}
__device__ __forceinline__ void tc_wait_ld() {
    asm volatile("tcgen05.wait::ld.sync.aligned;" ::: "memory");
}
__device__ __forceinline__ void tc_wait_st() {
    asm volatile("tcgen05.wait::st.sync.aligned;" ::: "memory");
}
__device__ __forceinline__ void ldtm32(uint32_t* r, uint32_t addr) {
    asm volatile(
        "tcgen05.ld.sync.aligned.32x32b.x32.b32 "
        "{%0, %1, %2, %3, %4, %5, %6, %7, %8, %9, %10, %11, %12, %13, %14, %15, "
        " %16, %17, %18, %19, %20, %21, %22, %23, %24, %25, %26, %27, %28, %29, %30, %31}, [%32];"
        : "=r"(r[0]), "=r"(r[1]), "=r"(r[2]), "=r"(r[3]), "=r"(r[4]), "=r"(r[5]),
          "=r"(r[6]), "=r"(r[7]), "=r"(r[8]), "=r"(r[9]), "=r"(r[10]), "=r"(r[11]),
          "=r"(r[12]), "=r"(r[13]), "=r"(r[14]), "=r"(r[15]), "=r"(r[16]), "=r"(r[17]),
          "=r"(r[18]), "=r"(r[19]), "=r"(r[20]), "=r"(r[21]), "=r"(r[22]), "=r"(r[23]),
          "=r"(r[24]), "=r"(r[25]), "=r"(r[26]), "=r"(r[27]), "=r"(r[28]), "=r"(r[29]),
          "=r"(r[30]), "=r"(r[31])
        : "r"(addr));
}
__device__ __forceinline__ void ldtm16(uint32_t* r, uint32_t addr) {
    asm volatile(
        "tcgen05.ld.sync.aligned.32x32b.x16.b32 "
        "{%0, %1, %2, %3, %4, %5, %6, %7, %8, %9, %10, %11, %12, %13, %14, %15}, [%16];"
        : "=r"(r[0]), "=r"(r[1]), "=r"(r[2]), "=r"(r[3]), "=r"(r[4]), "=r"(r[5]),
          "=r"(r[6]), "=r"(r[7]), "=r"(r[8]), "=r"(r[9]), "=r"(r[10]), "=r"(r[11]),
          "=r"(r[12]), "=r"(r[13]), "=r"(r[14]), "=r"(r[15])
        : "r"(addr));
}
__device__ __forceinline__ void sttm8(uint32_t addr, const uint32_t* r) {
    asm volatile(
        "tcgen05.st.sync.aligned.32x32b.x8.b32 [%0], {%1, %2, %3, %4, %5, %6, %7, %8};"
        :: "r"(addr), "r"(r[0]), "r"(r[1]), "r"(r[2]), "r"(r[3]),
           "r"(r[4]), "r"(r[5]), "r"(r[6]), "r"(r[7]) : "memory");
}
#endif  // HAS_TC

// SW64 K-major descriptor: layout=4, version=1, SBO=32, LBO=1
static __device__ __forceinline__ uint64_t make_desc64(uint32_t addr) {
    const uint64_t base =
        (uint64_t(4) << 61) | (uint64_t(1) << 46) | (uint64_t(32) << 32) | (uint64_t(1) << 16);
    return base | ((uint64_t)(addr >> 4) & 0x3FFF);
}

// idesc kind::f16: cF32(1<<4) | aBF16(1<<7) | bBF16(1<<10) | N=128 (16<<17) | M=128 (8<<24)
#define IDESC_BF16 0x08200490u

// ------- streaming GEMM smem layout (EMB / HEAD) -------
#define SM_TMEMP 0
#define SM_FULL0 16
#define SM_FULL1 24
#define SM_EMPT0 32
#define SM_EMPT1 40
#define SM_PART  256
#define SM_TILES 2048
#define STG_SZ   32768
#define OFF_AHI  0
#define OFF_ALO  8192
#define OFF_BHI  16384
#define OFF_BLO  24576
#define SMEM_GEMM (SM_TILES + 2 * STG_SZ)

// ------- fused layer smem layout (R12: resident W per phase, TS phase 2) ----------
#define L_F1    16           // + c*8
#define L_F2A   48
#define L_D1DN  56
#define L_E2DN  64
#define L_WBAR  72
#define L_B1S   128          // 512B
#define L_ASTG  1024         // + c*8192 : A hi stage per chunk (4 x 8KB)
#define L_WHI   33792        // 32KB resident W hi
#define L_WLO   66560        // 32KB resident W lo
#define SMEM_LAYER 99328
// TMEM: D1/D2 cols 0-127, A2hi 128-191, A2lo 192-255
#define TM_A2H  128
#define TM_A2L  192

__device__ __forceinline__ uint32_t pack_bf2(float a, float b) {
    __nv_bfloat162 h = __float22bfloat162_rn(make_float2(a, b));
    return *(uint32_t*)&h;
}

// ---------------- weight split (+ softmax scratch zero) ---------------------------
__global__ void split_w_k(const float* __restrict__ We, const float* __restrict__ W1,
                          const float* __restrict__ W2, const float* __restrict__ Wm)
{
    int i = blockIdx.x * 256 + threadIdx.x;
    if (i >= WT_TOTAL) return;
    if (i < NG) g_den[i] = 0.f;
    int base, n, k, K;
    if (i < 49152)       { base = 0;      int j = i;          K = 384; n = j / K; k = j % K; }
    else if (i < 114688) { int j = i - 49152;  int l = j >> 14; base = 49152 + l*16384;  j &= 16383; K = 128; n = j >> 7; k = j & 127; }
    else if (i < 180224) { int j = i - 114688; int l = j >> 14; base = 114688 + l*16384; j &= 16383; K = 128; n = j >> 7; k = j & 127; }
    else                 { base = 180224; int j = i - 180224;  K = 192; n = j / K; k = j % K; }
    float v;
    if (base == 0)           v = We[k * 128 + n];
    else if (base < 114688)  v = W1[(base - 49152) / 16384 * 16384 + k * 128 + n];
    else if (base < 180224)  v = W2[(base - 114688) / 16384 * 16384 + k * 128 + n];
    else                     v = Wm[k * 128 + n];

    __nv_bfloat16 hi = __float2bfloat16_rn(v);
    __nv_bfloat16 lo = __float2bfloat16_rn(v - __bfloat162float(hi));
    int chunk = k >> 5, kk = k & 31;
    uint32_t off = (uint32_t)n * 64u + (uint32_t)kk * 2u;
    off ^= ((off >> 3) & 0x30);               // SW64 swizzle
    int di = base + chunk * 4096 + (int)(off >> 1);
    g_wbhi[di] = hi;
    g_wblo[di] = lo;
}

// ---------------- scatter: g_xa[dst] += relu(x[src] + e) --------------------------
__global__ __launch_bounds__(256) void scatter_k(
    const int* __restrict__ src, const int* __restrict__ dst)
{
    const int warp = (blockIdx.x * blockDim.x + threadIdx.x) >> 5;
    const int lane = threadIdx.x & 31;
    if (warp >= E_) return;
    const int s = src[warp];
    const int d = dst[warp];
    float4 xv = *(const float4*)(g_x + (size_t)s * 128 + lane * 4);
    const __nv_bfloat162* ep = g_e2 + (size_t)warp * 64 + lane * 2;
    float2 e0 = __bfloat1622float2(ep[0]);
    float2 e1 = __bfloat1622float2(ep[1]);
    float4 m;
    m.x = fmaxf(xv.x + e0.x, 0.f);
    m.y = fmaxf(xv.y + e0.y, 0.f);
    m.z = fmaxf(xv.z + e1.x, 0.f);
    m.w = fmaxf(xv.w + e1.y, 0.f);
    atomicAdd((float4*)(g_xa + (size_t)d * 128 + lane * 4), m);
}

// ---------------- EMB(+edge blocks) / HEAD GEMM (streaming B pipeline) ------------
// MODE 0: grid = 2048 GEMM tiles + 2048 edge blocks. MODE 3: head; fuses
// exp(logit) -> outp and den atomic (max-free softmax; logits are O(1)).
template <int K, int MODE>
__global__ __launch_bounds__(288, 2) void tc_gemm_k(
    const float* __restrict__ A0, const float* __restrict__ A1,
    const float* __restrict__ A2, const int* __restrict__ n2g,
    const float* __restrict__ bias, const float* __restrict__ w2,
    const float* __restrict__ b2s, const float* __restrict__ eattr,
    float* __restrict__ outp, int woff)
{
    extern __shared__ __align__(1024) char smem[];
    const int tid  = threadIdx.x;

    // ---------------- edge-embedding blocks (MODE 0 only) ----------------
    if (MODE == 0 && blockIdx.x >= V_ / 128) {
        const int eb = blockIdx.x - V_ / 128;
        const int e0 = eb * 256;
        float* Ws = (float*)smem;
        float* Ae = (float*)(smem + 8192);
        float* bs = (float*)(smem + 24576);
        for (int i = tid; i < 2048; i += 288) Ws[i] = w2[i];
        for (int i = tid; i < 4096; i += 288) Ae[i] = eattr[(size_t)e0 * 16 + i];
        if (tid < 128) bs[tid] = b2s[tid];
        __syncthreads();
        if (tid < 256) {
            const int col = tid & 127, half = tid >> 7;
            float w[16];
            #pragma unroll
            for (int k = 0; k < 16; k++) w[k] = Ws[k * 128 + col];
            const float bb = bs[col];
            for (int ee = 0; ee < 128; ee++) {
                const int e = half * 128 + ee;
                const float4* a4 = (const float4*)&Ae[e * 16];
                float4 x0 = a4[0], x1 = a4[1], x2 = a4[2], x3 = a4[3];
                float s = bb;
                s = fmaf(x0.x, w[0],  s); s = fmaf(x0.y, w[1],  s);
                s = fmaf(x0.z, w[2],  s); s = fmaf(x0.w, w[3],  s);
                s = fmaf(x1.x, w[4],  s); s = fmaf(x1.y, w[5],  s);
                s = fmaf(x1.z, w[6],  s); s = fmaf(x1.w, w[7],  s);
                s = fmaf(x2.x, w[8],  s); s = fmaf(x2.y, w[9],  s);
                s = fmaf(x2.z, w[10], s); s = fmaf(x2.w, w[11], s);
                s = fmaf(x3.x, w[12], s); s = fmaf(x3.y, w[13], s);
                s = fmaf(x3.z, w[14], s); s = fmaf(x3.w, w[15], s);
                s = fmaxf(s, 0.f);
                float snb = __shfl_down_sync(0xffffffffu, s, 1);
                if ((col & 1) == 0) {
                    uint32_t pk = pack_bf2(s, snb);
                    *(uint32_t*)&g_e2[(size_t)(e0 + e) * 64 + (col >> 1)] = pk;
                }
            }
        }
        return;
    }

#if HAS_TC
    const uint32_t sb = smem_u32(smem);
    const int wid  = tid >> 5;
    const int lane = tid & 31;
    const int rowBase = blockIdx.x * 128;
    const int NCH = K / 32;

    if (wid == 0) { tc_alloc(sb + SM_TMEMP, 128); tc_relinquish(); }
    if (tid == 0) {
        mbar_init(sb + SM_FULL0, 257); mbar_init(sb + SM_FULL1, 257);
        mbar_init(sb + SM_EMPT0, 1);   mbar_init(sb + SM_EMPT1, 1);
    }
    __syncthreads();
    uint32_t tmem;
    asm volatile("ld.shared.b32 %0, [%1];" : "=r"(tmem) : "r"(sb + SM_TMEMP));

    if (tid < 256) {
        const int row  = tid >> 1;
        const int r    = rowBase + row;
        const int half = tid & 1;
        uint32_t bo = (uint32_t)row * 64u + (uint32_t)half * 32u;
        const uint32_t sw0 = bo ^ ((bo >> 3) & 0x30);
        bo += 16u;
        const uint32_t sw1 = bo ^ ((bo >> 3) & 0x30);
        int gg = 0;
        if (MODE == 0) gg = __ldg(n2g + r);

        for (int c = 0; c < NCH; c++) {
            const int s = c & 1;
            const int kb = c * 32 + half * 16;
            float4 av[4];
            if (MODE == 0) {
                const float* p = (kb < 128) ? A0 + (size_t)r * 128 + kb
                               : (kb < 256) ? A1 + (size_t)gg * 128 + (kb - 128)
                                            : A2 + (size_t)gg * 128 + (kb - 256);
                #pragma unroll
                for (int q = 0; q < 4; q++) av[q] = *(const float4*)(p + q * 4);
            } else {
                const float* p = (kb < 128) ? g_x + (size_t)r * 128 + kb
                                            : A0 + (size_t)r * 64 + (kb - 128);
                #pragma unroll
                for (int q = 0; q < 4; q++) av[q] = *(const float4*)(p + q * 4);
            }

            if (c >= 2) mbar_wait(sb + SM_EMPT0 + s * 8, ((c >> 1) + 1) & 1);

            const float* f = (const float*)av;
            uint32_t hi[8], lo[8];
            #pragma unroll
            for (int q = 0; q < 8; q++) {
                float a = f[2 * q], b = f[2 * q + 1];
                __nv_bfloat162 h = __float22bfloat162_rn(make_float2(a, b));
                hi[q] = *(uint32_t*)&h;
                lo[q] = pack_bf2(a - __bfloat162float(h.x), b - __bfloat162float(h.y));
            }
            char* stg = smem + SM_TILES + s * STG_SZ;
            *(uint4*)(stg + OFF_AHI + sw0) = *(uint4*)&hi[0];
            *(uint4*)(stg + OFF_AHI + sw1) = *(uint4*)&hi[4];
            *(uint4*)(stg + OFF_ALO + sw0) = *(uint4*)&lo[0];
            *(uint4*)(stg + OFF_ALO + sw1) = *(uint4*)&lo[4];

            fence_async_shared();
            mbar_arrive(sb + SM_FULL0 + s * 8);
        }
    } else if (tid == 256) {
        uint64_t dAhi[2], dAlo[2], dBhi[2], dBlo[2];
        #pragma unroll
        for (int s = 0; s < 2; s++) {
            uint32_t st = sb + SM_TILES + s * STG_SZ;
            dAhi[s] = make_desc64(st + OFF_AHI);
            dAlo[s] = make_desc64(st + OFF_ALO);
            dBhi[s] = make_desc64(st + OFF_BHI);
            dBlo[s] = make_desc64(st + OFF_BLO);
        }
        for (int c = 0; c < NCH; c++) {
            const int s = c & 1;
            if (c >= 2) mbar_wait(sb + SM_EMPT0 + s * 8, ((c >> 1) + 1) & 1);
            const uint32_t full = sb + SM_FULL0 + s * 8;
            mbar_arrive_tx(full, 16384);
            const uint32_t st = sb + SM_TILES + s * STG_SZ;
            bulk_g2s(st + OFF_BHI, g_wbhi + woff + c * 4096, 8192, full);
            bulk_g2s(st + OFF_BLO, g_wblo + woff + c * 4096, 8192, full);
            mbar_wait(full, (c >> 1) & 1);
            #pragma unroll
            for (int ks = 0; ks < 2; ks++) {
                const uint64_t o = ks * 2;
                int first = (c == 0 && ks == 0);
                mma_bf16(tmem, dAhi[s] + o, dBhi[s] + o, IDESC_BF16, first ? 0 : 1);
                mma_bf16(tmem, dAhi[s] + o, dBlo[s] + o, IDESC_BF16, 1);
                mma_bf16(tmem, dAlo[s] + o, dBhi[s] + o, IDESC_BF16, 1);
            }
            tc_commit(sb + SM_EMPT0 + s * 8);
        }
    }

    {
        const int L = NCH - 1;
        mbar_wait(sb + SM_EMPT0 + (L & 1) * 8, (L >> 1) & 1);
        tc_fence_after();
    }
    if (tid < 256) {
        const int sp = wid & 3;
        const int h  = wid >> 2;
        const int r  = rowBase + sp * 32 + lane;
        const int cb = h * 64;
        uint32_t regs[64];
        ldtm32(regs,      tmem + cb);
        ldtm32(regs + 32, tmem + cb + 32);
        tc_wait_ld();

        if (MODE == 3) {
            float p = 0.f;
            #pragma unroll
            for (int j = 0; j < 64; j++) {
                float t = fmaxf(__uint_as_float(regs[j]) + __ldg(bias + cb + j), 0.f);
                p = fmaf(t, __ldg(w2 + cb + j), p);
            }
            ((float*)(smem + SM_PART))[h * 128 + sp * 32 + lane] = p;
        } else {
            size_t base = (size_t)r * 128 + cb;
            #pragma unroll
            for (int j = 0; j < 64; j += 4) {
                float4 o;
                o.x = fmaxf(__uint_as_float(regs[j + 0]) + __ldg(bias + cb + j + 0), 0.f);
                o.y = fmaxf(__uint_as_float(regs[j + 1]) + __ldg(bias + cb + j + 1), 0.f);
                o.z = fmaxf(__uint_as_float(regs[j + 2]) + __ldg(bias + cb + j + 2), 0.f);
                o.w = fmaxf(__uint_as_float(regs[j + 3]) + __ldg(bias + cb + j + 3), 0.f);
                *(float4*)(g_x + base + j) = o;
                *(float4*)(g_xa + base + j) = o;     // seed x+agg accumulator
            }
        }
    }
    __syncthreads();
    if (MODE == 3 && tid < 128) {
        const float* part = (const float*)(smem + SM_PART);
        const int r = rowBase + tid;
        float lg = part[tid] + part[128 + tid] + b2s[0];
        float ex = expf(lg);
        outp[r] = ex;
        atomicAdd(&g_den[__ldg(n2g + r)], ex);
    }
    if (wid == 0) tc_dealloc(tmem, 128);

#else  // fallback (family-PTX pass only)
    const int rowBase = blockIdx.x * 128;
    if (tid >= 128) return;
    __shared__ float col[128];
    for (int m = 0; m < 128; m++) {
        const int r = rowBase + m;
        float acc = 0.f;
        for (int k = 0; k < K; k++) {
            float a;
            if (MODE == 0) {
                if (k < 128) a = A0[(size_t)r * 128 + k];
                else {
                    int gg = n2g[r];
                    a = (k < 256) ? A1[(size_t)gg * 128 + (k - 128)]
                                  : A2[(size_t)gg * 128 + (k - 256)];
                }
            } else {
                a = (k < 128) ? g_x[(size_t)r * 128 + k] : A0[(size_t)r * 64 + (k - 128)];
            }
            int chunk = k >> 5, kk = k & 31;
            uint32_t off = (uint32_t)tid * 64u + (uint32_t)kk * 2u;
            off ^= ((off >> 3) & 0x30);
            int di = woff + chunk * 4096 + (int)(off >> 1);
            float w = __bfloat162float(g_wbhi[di]) + __bfloat162float(g_wblo[di]);
            acc = fmaf(a, w, acc);
        }
        if (MODE == 3) {
            col[tid] = fmaxf(acc + bias[tid], 0.f) * w2[tid];
            __syncthreads();
            if (tid == 0) {
                float p = 0.f;
                for (int j = 0; j < 128; j++) p += col[j];
                float ex = expf(p + b2s[0]);
                outp[r] = ex;
                atomicAdd(&g_den[n2g[r]], ex);
            }
            __syncthreads();
        } else {
            float o = fmaxf(acc + bias[tid], 0.f);
            g_x[(size_t)r * 128 + tid] = o;
            g_xa[(size_t)r * 128 + tid] = o;
        }
    }
#endif
}

// ---------------- fused GINE layer (R12: resident-B, TS-mode phase 2) -------------
// x += relu(relu(xa@W1+b1)@W2+b2)
// phase1: A = bf16(xa) (smem), 2-term. phase2: A2 = hi/lo(relu(D1+b1)) in TMEM, 3-term.
__global__ __launch_bounds__(288, 2) void tc_layer_k(
    const float* __restrict__ b1, const float* __restrict__ b2,
    int woff1, int woff2, int seed)
{
#if HAS_TC
    extern __shared__ __align__(1024) char smem[];
    const uint32_t sb = smem_u32(smem);
    const int tid  = threadIdx.x;
    const int wid  = tid >> 5;
    const int lane = tid & 31;
    const int rowBase = blockIdx.x * 128;
    float* b1s = (float*)(smem + L_B1S);

    if (wid == 0) { tc_alloc(sb, 256); tc_relinquish(); }
    if (tid == 0) {
        #pragma unroll
        for (int c = 0; c < 4; c++) mbar_init(sb + L_F1 + c * 8, 256);
        mbar_init(sb + L_F2A, 256);
        mbar_init(sb + L_D1DN, 1);
        mbar_init(sb + L_E2DN, 1);
        mbar_init(sb + L_WBAR, 1);
    }
    if (tid >= 128 && tid < 256) b1s[tid - 128] = b1[tid - 128];
    __syncthreads();
    uint32_t tmem;
    asm volatile("ld.shared.b32 %0, [%1];" : "=r"(tmem) : "r"(sb));

    // ============ phase 1: D1 = bf16(xa) @ W1 (4 chunks, no backpressure) ============
    if (tid < 256) {
        const int row  = tid >> 1;
        const int r    = rowBase + row;
        const int half = tid & 1;
        uint32_t bo = (uint32_t)row * 64u + (uint32_t)half * 32u;
        const uint32_t sw0 = bo ^ ((bo >> 3) & 0x30);
        bo += 16u;
        const uint32_t sw1 = bo ^ ((bo >> 3) & 0x30);

        #pragma unroll
        for (int c = 0; c < 4; c++) {
            size_t off = (size_t)r * 128 + c * 32 + half * 16;
            float4 av[4];
            #pragma unroll
            for (int q = 0; q < 4; q++) av[q] = *(const float4*)(g_xa + off + q * 4);
            const float* f = (const float*)av;
            uint32_t hi[8];
            #pragma unroll
            for (int q = 0; q < 8; q++) hi[q] = pack_bf2(f[2 * q], f[2 * q + 1]);
            char* stg = smem + L_ASTG + c * 8192;
            *(uint4*)(stg + sw0) = *(uint4*)&hi[0];
            *(uint4*)(stg + sw1) = *(uint4*)&hi[4];
            fence_async_shared();
            mbar_arrive(sb + L_F1 + c * 8);
        }
    } else if (tid == 256) {
        mbar_arrive_tx(sb + L_WBAR, 65536);
        bulk_g2s(sb + L_WHI, g_wbhi + woff1, 32768, sb + L_WBAR);
        bulk_g2s(sb + L_WLO, g_wblo + woff1, 32768, sb + L_WBAR);
        uint64_t dA[4];
        #pragma unroll
        for (int c = 0; c < 4; c++) dA[c] = make_desc64(sb + L_ASTG + c * 8192);
        mbar_wait(sb + L_WBAR, 0);
        for (int c = 0; c < 4; c++) {
            mbar_wait(sb + L_F1 + c * 8, 0);
            uint64_t bh = make_desc64(sb + L_WHI + c * 8192);
            uint64_t bl = make_desc64(sb + L_WLO + c * 8192);
            #pragma unroll
            for (int ks = 0; ks < 2; ks++) {
                const uint64_t o = ks * 2;
                int first = (c == 0 && ks == 0);
                mma_bf16(tmem, dA[c] + o, bh + o, IDESC_BF16, first ? 0 : 1);
                mma_bf16(tmem, dA[c] + o, bl + o, IDESC_BF16, 1);
            }
        }
        tc_commit(sb + L_D1DN);
        // ---- W2 load overlaps producers' A2 conversion (W1 reads drained at D1DN)
        mbar_wait(sb + L_D1DN, 0);
        mbar_arrive_tx(sb + L_WBAR, 65536);
        bulk_g2s(sb + L_WHI, g_wbhi + woff2, 32768, sb + L_WBAR);
        bulk_g2s(sb + L_WLO, g_wblo + woff2, 32768, sb + L_WBAR);
        mbar_wait(sb + L_WBAR, 1);
        mbar_wait(sb + L_F2A, 0);
        tc_fence_after();
        for (int c = 0; c < 4; c++) {
            uint64_t bh = make_desc64(sb + L_WHI + c * 8192);
            uint64_t bl = make_desc64(sb + L_WLO + c * 8192);
            #pragma unroll
            for (int ks = 0; ks < 2; ks++) {
                const uint64_t o = ks * 2;
                const uint32_t aH = tmem + TM_A2H + c * 16 + ks * 8;
                const uint32_t aL = tmem + TM_A2L + c * 16 + ks * 8;
                int first = (c == 0 && ks == 0);
                // D2 overwrites D1's cols (D1 fully consumed by producers before F2A)
                mma_bf16_ts(tmem, aH, bh + o, IDESC_BF16, first ? 0 : 1);
                mma_bf16_ts(tmem, aH, bl + o, IDESC_BF16, 1);
                mma_bf16_ts(tmem, aL, bh + o, IDESC_BF16, 1);
            }
        }
        tc_commit(sb + L_E2DN);
    }

    // ============ phase 2 producers: A2 = hi/lo(relu(D1 + b1)) -> TMEM via STTM ======
    if (tid < 256) {
        mbar_wait(sb + L_D1DN, 0);
        tc_fence_after();
        const int sp = wid & 3;
        const int hh = wid >> 2;
        const uint32_t woffT = (uint32_t)sp << 21;   // subpartition lane-group offset
        #pragma unroll
        for (int c = 0; c < 4; c++) {
            uint32_t regs[16];
            ldtm16(regs, tmem + c * 32 + hh * 16);   // D1 cols
            tc_wait_ld();
            const int cb = c * 32 + hh * 16;
            uint32_t ahi[8], alo[8];
            #pragma unroll
            for (int q = 0; q < 8; q++) {
                float a = fmaxf(__uint_as_float(regs[2 * q])     + b1s[cb + 2 * q],     0.f);
                float b = fmaxf(__uint_as_float(regs[2 * q + 1]) + b1s[cb + 2 * q + 1], 0.f);
                __nv_bfloat162 h = __float22bfloat162_rn(make_float2(a, b));
                ahi[q] = *(uint32_t*)&h;
                alo[q] = pack_bf2(a - __bfloat162float(h.x), b - __bfloat162float(h.y));
            }
            sttm8(tmem + woffT + TM_A2H + c * 16 + hh * 8, ahi);
            sttm8(tmem + woffT + TM_A2L + c * 16 + hh * 8, alo);
        }
        tc_wait_st();
        tc_fence_before();
        mbar_arrive(sb + L_F2A);
    }

    // ============ epilogue: g_x += relu(D2 + b2); seed g_xa ============
    mbar_wait(sb + L_E2DN, 0);
    tc_fence_after();
    if (tid < 256) {
        const int sp = wid & 3;
        const int h  = wid >> 2;
        const int r  = rowBase + sp * 32 + lane;
        const int cb = h * 64;
        uint32_t regs[64];
        ldtm32(regs,      tmem + cb);            // D2 lives in cols 0-127
        ldtm32(regs + 32, tmem + cb + 32);
        tc_wait_ld();
        size_t base = (size_t)r * 128 + cb;
        #pragma unroll
        for (int j = 0; j < 64; j += 4) {
            float4 o;
            o.x = fmaxf(__uint_as_float(regs[j + 0]) + __ldg(b2 + cb + j + 0), 0.f);
            o.y = fmaxf(__uint_as_float(regs[j + 1]) + __ldg(b2 + cb + j + 1), 0.f);
            o.z = fmaxf(__uint_as_float(regs[j + 2]) + __ldg(b2 + cb + j + 2), 0.f);
            o.w = fmaxf(__uint_as_float(regs[j + 3]) + __ldg(b2 + cb + j + 3), 0.f);
            float4 x0 = *(const float4*)(g_x + base + j);
            o.x += x0.x; o.y += x0.y; o.z += x0.z; o.w += x0.w;
            *(float4*)(g_x + base + j) = o;
            if (seed) *(float4*)(g_xa + base + j) = o;
        }
    }
    __syncthreads();
    if (wid == 0) tc_dealloc(tmem, 256);

#else  // fallback (family-PTX pass only)
    const int tid = threadIdx.x;
    const int rowBase = blockIdx.x * 128;
    if (tid >= 128) return;
    __shared__ float hrow[128];
    for (int m = 0; m < 128; m++) {
        const int r = rowBase + m;
        float acc = 0.f;
        for (int k = 0; k < 128; k++) {
            float a = g_xa[(size_t)r * 128 + k];
            int chunk = k >> 5, kk = k & 31;
            uint32_t off = (uint32_t)tid * 64u + (uint32_t)kk * 2u;
            off ^= ((off >> 3) & 0x30);
            int di = woff1 + chunk * 4096 + (int)(off >> 1);
            acc = fmaf(a, __bfloat162float(g_wbhi[di]) + __bfloat162float(g_wblo[di]), acc);
        }
        hrow[tid] = fmaxf(acc + b1[tid], 0.f);
        __syncthreads();
        float acc2 = 0.f;
        for (int k = 0; k < 128; k++) {
            int chunk = k >> 5, kk = k & 31;
            uint32_t off = (uint32_t)tid * 64u + (uint32_t)kk * 2u;
            off ^= ((off >> 3) & 0x30);
            int di = woff2 + chunk * 4096 + (int)(off >> 1);
            acc2 = fmaf(hrow[k], __bfloat162float(g_wbhi[di]) + __bfloat162float(g_wblo[di]), acc2);
        }
        float xn = g_x[(size_t)r * 128 + tid] + fmaxf(acc2 + b2[tid], 0.f);
        g_x[(size_t)r * 128 + tid] = xn;
        if (seed) g_xa[(size_t)r * 128 + tid] = xn;
        __syncthreads();
    }
#endif
}

// ---------------- segment softmax finish -------------------------------------------
__global__ void seg_div_k(const int* __restrict__ n2g, float* __restrict__ out) {
    int i = blockIdx.x * blockDim.x + threadIdx.x;
    if (i >= V_) return;
    out[i] = out[i] / g_den[n2g[i]];
}

// ---------------- launch -----------------------------------------------------------
extern "C" void kernel_launch(void* const* d_in, const int* in_sizes, int n_in,
                              void* d_out, int out_size)
{
    const float* x_inp   = (const float*)d_in[0];
    const int*   eidx    = (const int*)  d_in[1];
    const float* eattr   = (const float*)d_in[2];
    const float* x_upd   = (const float*)d_in[3];
    const float* Zc      = (const float*)d_in[4];
    const float* Zb      = (const float*)d_in[5];
    const int*   n2g     = (const int*)  d_in[6];
    const float* W_emb   = (const float*)d_in[7];
    const float* b_emb   = (const float*)d_in[8];
    const float* W_edge  = (const float*)d_in[9];
    const float* b_edge  = (const float*)d_in[10];
    const float* W1      = (const float*)d_in[11];
    const float* b1      = (const float*)d_in[12];
    const float* W2      = (const float*)d_in[13];
    const float* b2      = (const float*)d_in[14];
    const float* W_mlp1  = (const float*)d_in[15];
    const float* b_mlp1  = (const float*)d_in[16];
    const float* W_mlp2  = (const float*)d_in[17];
    const float* b_mlp2  = (const float*)d_in[18];
    float* out = (float*)d_out;

    cudaFuncSetAttribute(tc_gemm_k<384, 0>, cudaFuncAttributeMaxDynamicSharedMemorySize, SMEM_GEMM);
    cudaFuncSetAttribute(tc_gemm_k<192, 3>, cudaFuncAttributeMaxDynamicSharedMemorySize, SMEM_GEMM);
    cudaFuncSetAttribute(tc_layer_k,        cudaFuncAttributeMaxDynamicSharedMemorySize, SMEM_LAYER);

    const int GB = V_ / 128;   // 2048 tiles

    split_w_k<<<(WT_TOTAL + 255) / 256, 256>>>(W_emb, W1, W2, W_mlp1);
    tc_gemm_k<384, 0><<<GB + 2048, 288, SMEM_GEMM>>>(x_upd, Zc, Zb, n2g, b_emb,
                                                     W_edge, b_edge, eattr, nullptr, 0);
    for (int l = 0; l < 4; l++) {
        scatter_k<<<E_ / 8, 256>>>(eidx, eidx + E_);
        tc_layer_k<<<GB, 288, SMEM_LAYER>>>(b1 + (size_t)l * 128, b2 + (size_t)l * 128,
                                            49152 + l * 16384, 114688 + l * 16384,
                                            l < 3 ? 1 : 0);
    }
    tc_gemm_k<192, 3><<<GB, 288, SMEM_GEMM>>>(x_inp, nullptr, nullptr, n2g,
                                              b_mlp1, W_mlp2, b_mlp2, nullptr, out, 180224);

    seg_div_k<<<V_ / 256, 256>>>(n2g, out);
}